// round 5
// baseline (speedup 1.0000x reference)
#include <cuda_runtime.h>
#include <math.h>

#define B_  32
#define S_  512
#define I_  256
#define H_  1024
#define O_  256
#define L_  3
#define G3H (3*H_)
#define NCTA_REC 128

typedef unsigned long long ull;

// ---------------- f32x2 packed math (sm_103a FFMA2 path) ----------------
__device__ __forceinline__ ull pk2(float x, float y) {
    ull r;
    asm("mov.b64 %0, {%1, %2};" : "=l"(r)
        : "r"(__float_as_uint(x)), "r"(__float_as_uint(y)));
    return r;
}
__device__ __forceinline__ void upk2(ull p, float& x, float& y) {
    unsigned int a, b;
    asm("mov.b64 {%0, %1}, %2;" : "=r"(a), "=r"(b) : "l"(p));
    x = __uint_as_float(a); y = __uint_as_float(b);
}
__device__ __forceinline__ ull ffma2(ull a, ull b, ull c) {
    ull d;
    asm("fma.rn.f32x2 %0, %1, %2, %3;" : "=l"(d) : "l"(a), "l"(b), "l"(c));
    return d;
}

// ---------------- device scratch (allocation-free) ----------------
__device__ float g_xT[(size_t)S_*B_*I_];        // 16 MB  transposed x -> [s*B+b][i]
__device__ float g_xp[(size_t)S_*B_*G3H];       // 201 MB input projections [s*B+b][3H]
__device__ float g_hs[(size_t)S_*B_*H_];        // 64 MB  layer output sequence [s*B+b][h]
__device__ float g_h [B_*H_];                   // hidden, [b][j] layout
__device__ float g_rh[B_*H_];                   // r*h,    [b][j] layout
__device__ unsigned int g_flags[128];           // barrier flags (zero-init)

// ---------------- fast grid barrier: flag line + one-warp poll ----------------
// epoch is strictly increasing across the whole run (per-layer base offset),
// so flags never need resetting and ">=" makes reuse safe.
__device__ __forceinline__ void fast_barrier(unsigned int epoch, int w, int lane)
{
    __syncthreads();
    __threadfence();                       // release all this CTA's writes
    if (threadIdx.x == 0)
        ((volatile unsigned int*)g_flags)[blockIdx.x] = epoch;
    if (w == 0) {
        const uint4* f4 = (const uint4*)g_flags;
        for (;;) {
            uint4 v = __ldcg(&f4[lane]);   // 32 lanes x 4 flags = 128
            bool ok = (v.x >= epoch) & (v.y >= epoch) &
                      (v.z >= epoch) & (v.w >= epoch);
            if (__all_sync(0xffffffffu, ok)) break;
            __nanosleep(32);
        }
    }
    __syncthreads();
    __threadfence();                       // acquire before reading peer data
}

// ---------------- transpose x[b][s][i] -> xT[(s*B+b)][i] ----------------
__global__ void transpose_kernel(const float4* __restrict__ x, float4* __restrict__ xT)
{
    int idx = blockIdx.x * blockDim.x + threadIdx.x;   // over S*B*I/4
    int i4 = idx & 63;          // I/4 = 64
    int m  = idx >> 6;          // m = s*B + b
    int b  = m & 31;
    int s  = m >> 5;
    xT[idx] = x[(size_t)(b * S_ + s) * 64 + i4];
}

// ---------------- SGEMM: C[m][n] = sum_k A[m][k]*W[n][k] + bias[n] ----------------
__global__ void __launch_bounds__(256) gemm_kernel(
    const float* __restrict__ A, const float* __restrict__ W,
    const float* __restrict__ bias, float* __restrict__ C,
    int K, int N, int mode)
{
    __shared__ float As[16][128];
    __shared__ float Bs[16][128];

    const int tid  = threadIdx.x;
    const int bx   = blockIdx.x;   // N tile
    const int by   = blockIdx.y;   // M tile
    const int lrow = tid >> 1;
    const int lc4  = (tid & 1) << 2;

    const float* Arow = A + (size_t)(by * 128 + lrow) * K + lc4;
    const float* Wrow = W + (size_t)(bx * 128 + lrow) * K + lc4;

    const int tx = tid & 15;
    const int ty = tid >> 4;

    ull acc2[8][4];
#pragma unroll
    for (int i = 0; i < 8; i++)
#pragma unroll
        for (int j = 0; j < 4; j++) acc2[i][j] = 0ull;

    for (int kt = 0; kt < K; kt += 16) {
        float4 a0 = *(const float4*)(Arow + kt);
        float4 a1 = *(const float4*)(Arow + kt + 8);
        float4 w0 = *(const float4*)(Wrow + kt);
        float4 w1 = *(const float4*)(Wrow + kt + 8);
        __syncthreads();
        As[lc4 + 0][lrow] = a0.x; As[lc4 + 1][lrow] = a0.y;
        As[lc4 + 2][lrow] = a0.z; As[lc4 + 3][lrow] = a0.w;
        As[lc4 + 8][lrow] = a1.x; As[lc4 + 9][lrow] = a1.y;
        As[lc4 +10][lrow] = a1.z; As[lc4 +11][lrow] = a1.w;
        Bs[lc4 + 0][lrow] = w0.x; Bs[lc4 + 1][lrow] = w0.y;
        Bs[lc4 + 2][lrow] = w0.z; Bs[lc4 + 3][lrow] = w0.w;
        Bs[lc4 + 8][lrow] = w1.x; Bs[lc4 + 9][lrow] = w1.y;
        Bs[lc4 +10][lrow] = w1.z; Bs[lc4 +11][lrow] = w1.w;
        __syncthreads();
#pragma unroll
        for (int k = 0; k < 16; k++) {
            float4 av0 = *(const float4*)&As[k][ty * 8];
            float4 av1 = *(const float4*)&As[k][ty * 8 + 4];
            float4 bv0 = *(const float4*)&Bs[k][tx * 8];
            float4 bv1 = *(const float4*)&Bs[k][tx * 8 + 4];
            ull pb0 = pk2(bv0.x, bv0.y);
            ull pb1 = pk2(bv0.z, bv0.w);
            ull pb2 = pk2(bv1.x, bv1.y);
            ull pb3 = pk2(bv1.z, bv1.w);
            float a_[8] = {av0.x, av0.y, av0.z, av0.w, av1.x, av1.y, av1.z, av1.w};
#pragma unroll
            for (int i = 0; i < 8; i++) {
                ull pa = pk2(a_[i], a_[i]);
                acc2[i][0] = ffma2(pa, pb0, acc2[i][0]);
                acc2[i][1] = ffma2(pa, pb1, acc2[i][1]);
                acc2[i][2] = ffma2(pa, pb2, acc2[i][2]);
                acc2[i][3] = ffma2(pa, pb3, acc2[i][3]);
            }
        }
    }

    const int mbase = by * 128 + ty * 8;
    const int nbase = bx * 128 + tx * 8;
    float bb[8];
#pragma unroll
    for (int j = 0; j < 8; j++) bb[j] = bias[nbase + j];

#pragma unroll
    for (int i = 0; i < 8; i++) {
        int m = mbase + i;
        float cv[8];
#pragma unroll
        for (int j = 0; j < 4; j++) upk2(acc2[i][j], cv[2*j], cv[2*j+1]);
#pragma unroll
        for (int j = 0; j < 8; j++) {
            float v = cv[j] + bb[j];
            if (mode == 0) {
                C[(size_t)m * N + (nbase + j)] = v;
            } else {
                int b = m & 31, s = m >> 5;
                C[(size_t)((b << 9) + s) * O_ + (nbase + j)] = v;
            }
        }
    }
}

// ---------------- persistent GRU recurrence (one layer) ----------------
// 128 CTAs (1/SM, co-resident), 512 threads = 16 warps.
// CTA owns gate columns [cta*8, cta*8+8) of z, r, g.
// Warp w = k-slice [w*64, w*64+64). lane = batch b.
// k processed in 2 chunks of 32 so operand regs (v2[16]) + accumulators
// (acc[16]) stay under the 128-reg cap -> no local spill.
__global__ void __launch_bounds__(512, 1) gru_rec_kernel(
    const float* __restrict__ Wh,      // [3H][H]
    const float* __restrict__ xp,      // [S*B][3H] (bias folded in)
    float*       __restrict__ hs,      // [S*B][H]
    const float* __restrict__ h0,      // [B][L][H]
    int layer,
    float*       __restrict__ hlast,   // d_out + B*S*O : [B][L][H]
    unsigned int ebase)                // barrier epoch base for this launch
{
    extern __shared__ float sh[];
    ull*   ws  = (ull*)sh;             // [24 cols][512 k-pairs]   96 KB
    float* red = sh + 24576;           // [16][32][17] partials    34 KB
    __shared__ float s_z[B_ * 8];      // z values   [b][c]
    __shared__ float s_h[B_ * 8];      // h (own 8 cols) [b][c]

    const int tid  = threadIdx.x;
    const int cta  = blockIdx.x;
    const int w    = tid >> 5;         // 0..15 : k-slice AND epilogue column
    const int lane = tid & 31;         // batch b
    const int j0   = cta * 8;
    const int k0   = w * 64;

    // ---- preload this CTA's 24 weight rows, packed k-pairs ----
    for (int rr = w; rr < 24; rr += 16) {
        int row = (rr < 8)  ? (j0 + rr)
                : (rr < 16) ? (H_ + j0 + (rr - 8))
                            : (2 * H_ + j0 + (rr - 16));
        const float2* src = (const float2*)(Wh + (size_t)row * H_);
        for (int i = lane; i < 512; i += 32) {
            float2 v = __ldg(src + i);
            ws[rr * 512 + i] = pk2(v.x, v.y);
        }
    }

    // ---- init hidden state ----
    {
        int i = cta * 512 + tid;
        if (i < B_ * H_) {
            int b = i >> 10, j = i & 1023;
            g_h[i] = h0[(b * L_ + layer) * H_ + j];
        }
        if (w < 8) s_h[lane * 8 + w] = h0[(lane * L_ + layer) * H_ + j0 + w];
    }
    unsigned int ep = ebase;
    fast_barrier(++ep, w, lane);

    for (int s = 0; s < S_; s++) {
        // ---- prefetch xp for this thread's epilogue column ----
        float xpA, xpB = 0.f;
        {
            const size_t base = (size_t)(s * B_ + lane) * G3H;
            int col = (w < 8) ? (j0 + w) : (H_ + j0 + (w - 8));
            xpA = __ldg(&xp[base + col]);
            if (w < 8) xpB = __ldg(&xp[base + 2 * H_ + j0 + w]);
        }

        // ---- phase A: 16 cols (8 z + 8 r), this warp's 64 k, chunked ----
        {
            ull acc[16];
#pragma unroll
            for (int c = 0; c < 16; c++) acc[c] = 0ull;
#pragma unroll
            for (int chunk = 0; chunk < 2; chunk++) {
                ull v2[16];
                const float4* hp = (const float4*)(g_h + lane * H_ + k0 + chunk * 32);
#pragma unroll
                for (int i = 0; i < 8; i++) {
                    float4 v = __ldcg(hp + i);
                    v2[2*i]   = pk2(v.x, v.y);
                    v2[2*i+1] = pk2(v.z, v.w);
                }
                const int kpb = (k0 >> 1) + chunk * 16;
#pragma unroll 2
                for (int c = 0; c < 16; c++) {
                    const ulonglong2* wp = (const ulonglong2*)(ws + c * 512 + kpb);
                    ull a = acc[c];
#pragma unroll
                    for (int i = 0; i < 8; i++) {
                        ulonglong2 u = wp[i];
                        a = ffma2(v2[2*i],   u.x, a);
                        a = ffma2(v2[2*i+1], u.y, a);
                    }
                    acc[c] = a;
                }
            }
#pragma unroll
            for (int c = 0; c < 16; c++) {
                float x, y; upk2(acc[c], x, y);
                red[(c * 32 + lane) * 17 + w] = x + y;
            }
        }
        __syncthreads();

        // ---- reduce + gate epilogue: thread (c=w, b=lane) ----
        {
            const float* rp = red + (w * 32 + lane) * 17;
            float sum = xpA;
#pragma unroll
            for (int t = 0; t < 16; t++) sum += rp[t];
            float sg = 1.f / (1.f + expf(-sum));
            if (w < 8) {
                s_z[lane * 8 + w] = sg;
            } else {
                int c = w - 8;
                g_rh[lane * H_ + j0 + c] = sg * s_h[lane * 8 + c];
            }
        }
        fast_barrier(++ep, w, lane);

        // ---- phase B: 8 g cols, chunked ----
        {
            ull acc[8];
#pragma unroll
            for (int c = 0; c < 8; c++) acc[c] = 0ull;
#pragma unroll
            for (int chunk = 0; chunk < 2; chunk++) {
                ull v2[16];
                const float4* rp4 = (const float4*)(g_rh + lane * H_ + k0 + chunk * 32);
#pragma unroll
                for (int i = 0; i < 8; i++) {
                    float4 v = __ldcg(rp4 + i);
                    v2[2*i]   = pk2(v.x, v.y);
                    v2[2*i+1] = pk2(v.z, v.w);
                }
                const int kpb = (k0 >> 1) + chunk * 16;
#pragma unroll 2
                for (int c = 0; c < 8; c++) {
                    const ulonglong2* wp = (const ulonglong2*)(ws + (16 + c) * 512 + kpb);
                    ull a = acc[c];
#pragma unroll
                    for (int i = 0; i < 8; i++) {
                        ulonglong2 u = wp[i];
                        a = ffma2(v2[2*i],   u.x, a);
                        a = ffma2(v2[2*i+1], u.y, a);
                    }
                    acc[c] = a;
                }
            }
#pragma unroll
            for (int c = 0; c < 8; c++) {
                float x, y; upk2(acc[c], x, y);
                red[(c * 32 + lane) * 17 + w] = x + y;
            }
        }
        __syncthreads();

        // ---- reduce + h update: thread (c=w<8, b=lane) ----
        if (w < 8) {
            const float* rp = red + (w * 32 + lane) * 17;
            float sum = xpB;
#pragma unroll
            for (int t = 0; t < 16; t++) sum += rp[t];
            float gg = tanhf(sum);
            float zz = s_z[lane * 8 + w];
            float ho = s_h[lane * 8 + w];
            float hn = zz * ho + (1.f - zz) * gg;
            int j = j0 + w;
            s_h[lane * 8 + w] = hn;
            g_h[lane * H_ + j] = hn;
            hs[(size_t)(s * B_ + lane) * H_ + j] = hn;
            if (s == S_ - 1) hlast[(size_t)(lane * L_ + layer) * H_ + j] = hn;
        }
        fast_barrier(++ep, w, lane);
    }
}

// ---------------- host launch ----------------
extern "C" void kernel_launch(void* const* d_in, const int* in_sizes, int n_in,
                              void* d_out, int out_size)
{
    const float* x    = (const float*)d_in[0];
    const float* h0   = (const float*)d_in[1];
    const float* Wx0  = (const float*)d_in[2];
    const float* Wh0  = (const float*)d_in[3];
    const float* bh0  = (const float*)d_in[4];
    const float* Wx   = (const float*)d_in[5];
    const float* Wh   = (const float*)d_in[6];
    const float* bh   = (const float*)d_in[7];
    const float* Wout = (const float*)d_in[8];
    const float* bout = (const float*)d_in[9];

    float* out = (float*)d_out;
    float* hid = out + (size_t)B_ * S_ * O_;

    float *p_xT, *p_xp, *p_hs;
    cudaGetSymbolAddress((void**)&p_xT, g_xT);
    cudaGetSymbolAddress((void**)&p_xp, g_xp);
    cudaGetSymbolAddress((void**)&p_hs, g_hs);

    // reset barrier flags so epochs restart cleanly every call
    unsigned int* p_flags;
    cudaGetSymbolAddress((void**)&p_flags, g_flags);
    cudaMemsetAsync(p_flags, 0, 128 * sizeof(unsigned int));

    const int rec_smem = 24576 * 4 + 16 * 32 * 17 * 4;   // 98304 + 34816 = 133120
    cudaFuncSetAttribute(gru_rec_kernel,
                         cudaFuncAttributeMaxDynamicSharedMemorySize, rec_smem);

    // 1) transpose x -> [s*B+b][i]
    transpose_kernel<<<4096, 256>>>((const float4*)x, (float4*)p_xT);

    // 2) layer 0
    gemm_kernel<<<dim3(G3H / 128, (S_ * B_) / 128), 256>>>(p_xT, Wx0, bh0, p_xp, I_, G3H, 0);
    gru_rec_kernel<<<NCTA_REC, 512, rec_smem>>>(Wh0, p_xp, p_hs, h0, 0, hid, 0u);

    // 3) layer 1
    gemm_kernel<<<dim3(G3H / 128, (S_ * B_) / 128), 256>>>(p_hs, Wx, bh, p_xp, H_, G3H, 0);
    gru_rec_kernel<<<NCTA_REC, 512, rec_smem>>>(Wh, p_xp, p_hs, h0, 1, hid, 4096u);

    // 4) layer 2
    gemm_kernel<<<dim3(G3H / 128, (S_ * B_) / 128), 256>>>(
        p_hs, Wx + (size_t)3 * H_ * H_, bh + 3 * H_, p_xp, H_, G3H, 0);
    gru_rec_kernel<<<NCTA_REC, 512, rec_smem>>>(
        Wh + (size_t)3 * H_ * H_, p_xp, p_hs, h0, 2, hid, 8192u);

    // 5) output head -> d_out [B,S,O]
    gemm_kernel<<<dim3(O_ / 128, (S_ * B_) / 128), 256>>>(p_hs, Wout, bout, out, H_, O_, 1);
}

// round 6
// speedup vs baseline: 1.0667x; 1.0667x over previous
#include <cuda_runtime.h>
#include <math.h>

#define B_  32
#define S_  512
#define I_  256
#define H_  1024
#define O_  256
#define L_  3
#define G3H (3*H_)
#define NCTA_REC 128

typedef unsigned long long ull;

// ---------------- f32x2 packed math (sm_103a FFMA2 path) ----------------
__device__ __forceinline__ ull pk2(float x, float y) {
    ull r;
    asm("mov.b64 %0, {%1, %2};" : "=l"(r)
        : "r"(__float_as_uint(x)), "r"(__float_as_uint(y)));
    return r;
}
__device__ __forceinline__ void upk2(ull p, float& x, float& y) {
    unsigned int a, b;
    asm("mov.b64 {%0, %1}, %2;" : "=r"(a), "=r"(b) : "l"(p));
    x = __uint_as_float(a); y = __uint_as_float(b);
}
__device__ __forceinline__ ull ffma2(ull a, ull b, ull c) {
    ull d;
    asm("fma.rn.f32x2 %0, %1, %2, %3;" : "=l"(d) : "l"(a), "l"(b), "l"(c));
    return d;
}
__device__ __forceinline__ ull fadd2(ull a, ull b) {
    ull d;
    asm("add.rn.f32x2 %0, %1, %2;" : "=l"(d) : "l"(a), "l"(b));
    return d;
}

// ---------------- device scratch (allocation-free) ----------------
__device__ float g_xT[(size_t)S_*B_*I_];        // 16 MB  transposed x -> [s*B+b][i]
__device__ float g_xp[(size_t)S_*B_*G3H];       // 201 MB input projections [s*B+b][3H]
__device__ float g_hs[(size_t)S_*B_*H_];        // 64 MB  layer output sequence [s*B+b][h]
__device__ float g_h [B_*H_];                   // hidden, [b][j] layout
__device__ float g_rh[B_*H_];                   // r*h,    [b][j] layout
__device__ unsigned int g_barcount;
__device__ unsigned int g_bargen;

// ---------------- grid-wide barrier (proven R2 version) ----------------
__device__ __forceinline__ void grid_barrier()
{
    __syncthreads();
    if (threadIdx.x == 0) {
        unsigned int gen = *(volatile unsigned int*)&g_bargen;
        __threadfence();
        if (atomicAdd(&g_barcount, 1u) == gridDim.x - 1u) {
            g_barcount = 0u;
            __threadfence();
            atomicAdd(&g_bargen, 1u);
        } else {
            while (*(volatile unsigned int*)&g_bargen == gen) { __nanosleep(32); }
        }
        __threadfence();
    }
    __syncthreads();
}

// ---------------- transpose x[b][s][i] -> xT[(s*B+b)][i] ----------------
__global__ void transpose_kernel(const float4* __restrict__ x, float4* __restrict__ xT)
{
    int idx = blockIdx.x * blockDim.x + threadIdx.x;   // over S*B*I/4
    int i4 = idx & 63;          // I/4 = 64
    int m  = idx >> 6;          // m = s*B + b
    int b  = m & 31;
    int s  = m >> 5;
    xT[idx] = x[(size_t)(b * S_ + s) * 64 + i4];
}

// ---------------- SGEMM: C[m][n] = sum_k A[m][k]*W[n][k] + bias[n] ----------------
__global__ void __launch_bounds__(256) gemm_kernel(
    const float* __restrict__ A, const float* __restrict__ W,
    const float* __restrict__ bias, float* __restrict__ C,
    int K, int N, int mode)
{
    __shared__ float As[16][128];
    __shared__ float Bs[16][128];

    const int tid  = threadIdx.x;
    const int bx   = blockIdx.x;   // N tile
    const int by   = blockIdx.y;   // M tile
    const int lrow = tid >> 1;
    const int lc4  = (tid & 1) << 2;

    const float* Arow = A + (size_t)(by * 128 + lrow) * K + lc4;
    const float* Wrow = W + (size_t)(bx * 128 + lrow) * K + lc4;

    const int tx = tid & 15;
    const int ty = tid >> 4;

    ull acc2[8][4];
#pragma unroll
    for (int i = 0; i < 8; i++)
#pragma unroll
        for (int j = 0; j < 4; j++) acc2[i][j] = 0ull;

    for (int kt = 0; kt < K; kt += 16) {
        float4 a0 = *(const float4*)(Arow + kt);
        float4 a1 = *(const float4*)(Arow + kt + 8);
        float4 w0 = *(const float4*)(Wrow + kt);
        float4 w1 = *(const float4*)(Wrow + kt + 8);
        __syncthreads();
        As[lc4 + 0][lrow] = a0.x; As[lc4 + 1][lrow] = a0.y;
        As[lc4 + 2][lrow] = a0.z; As[lc4 + 3][lrow] = a0.w;
        As[lc4 + 8][lrow] = a1.x; As[lc4 + 9][lrow] = a1.y;
        As[lc4 +10][lrow] = a1.z; As[lc4 +11][lrow] = a1.w;
        Bs[lc4 + 0][lrow] = w0.x; Bs[lc4 + 1][lrow] = w0.y;
        Bs[lc4 + 2][lrow] = w0.z; Bs[lc4 + 3][lrow] = w0.w;
        Bs[lc4 + 8][lrow] = w1.x; Bs[lc4 + 9][lrow] = w1.y;
        Bs[lc4 +10][lrow] = w1.z; Bs[lc4 +11][lrow] = w1.w;
        __syncthreads();
#pragma unroll
        for (int k = 0; k < 16; k++) {
            float4 av0 = *(const float4*)&As[k][ty * 8];
            float4 av1 = *(const float4*)&As[k][ty * 8 + 4];
            float4 bv0 = *(const float4*)&Bs[k][tx * 8];
            float4 bv1 = *(const float4*)&Bs[k][tx * 8 + 4];
            ull pb0 = pk2(bv0.x, bv0.y);
            ull pb1 = pk2(bv0.z, bv0.w);
            ull pb2 = pk2(bv1.x, bv1.y);
            ull pb3 = pk2(bv1.z, bv1.w);
            float a_[8] = {av0.x, av0.y, av0.z, av0.w, av1.x, av1.y, av1.z, av1.w};
#pragma unroll
            for (int i = 0; i < 8; i++) {
                ull pa = pk2(a_[i], a_[i]);
                acc2[i][0] = ffma2(pa, pb0, acc2[i][0]);
                acc2[i][1] = ffma2(pa, pb1, acc2[i][1]);
                acc2[i][2] = ffma2(pa, pb2, acc2[i][2]);
                acc2[i][3] = ffma2(pa, pb3, acc2[i][3]);
            }
        }
    }

    const int mbase = by * 128 + ty * 8;
    const int nbase = bx * 128 + tx * 8;
    float bb[8];
#pragma unroll
    for (int j = 0; j < 8; j++) bb[j] = bias[nbase + j];

#pragma unroll
    for (int i = 0; i < 8; i++) {
        int m = mbase + i;
        float cv[8];
#pragma unroll
        for (int j = 0; j < 4; j++) upk2(acc2[i][j], cv[2*j], cv[2*j+1]);
#pragma unroll
        for (int j = 0; j < 8; j++) {
            float v = cv[j] + bb[j];
            if (mode == 0) {
                C[(size_t)m * N + (nbase + j)] = v;
            } else {
                int b = m & 31, s = m >> 5;
                C[(size_t)((b << 9) + s) * O_ + (nbase + j)] = v;
            }
        }
    }
}

// ---------------- persistent GRU recurrence (one layer) ----------------
// 128 CTAs (1/SM, co-resident), 512 threads = 16 warps.
// CTA owns gate columns [cta*8, cta*8+8) of z, r, g.
// Warp w = k-slice [w*64, w*64+64). lane = batch b.
// v2[32] loaded ONCE per phase; weight-load loops unrolled only 4x so
// ptxas doesn't batch 16 LDS.128 (transient regs) -> stays under 128 regs.
__global__ void __launch_bounds__(512, 1) gru_rec_kernel(
    const float* __restrict__ Wh,      // [3H][H]
    const float* __restrict__ xp,      // [S*B][3H] (bias folded in)
    float*       __restrict__ hs,      // [S*B][H]
    const float* __restrict__ h0,      // [B][L][H]
    int layer,
    float*       __restrict__ hlast)   // d_out + B*S*O : [B][L][H]
{
    extern __shared__ float sh[];
    ull*   ws  = (ull*)sh;             // [24 cols][512 k-pairs]   96 KB
    float* red = sh + 24576;           // [16][32][17] partials    34 KB
    __shared__ float s_z[B_ * 8];      // z values   [b][c]
    __shared__ float s_h[B_ * 8];      // h (own 8 cols) [b][c]

    const int tid  = threadIdx.x;
    const int cta  = blockIdx.x;
    const int w    = tid >> 5;         // 0..15 : k-slice AND epilogue column
    const int lane = tid & 31;         // batch b
    const int j0   = cta * 8;
    const int k0   = w * 64;

    // ---- preload this CTA's 24 weight rows, packed k-pairs ----
    for (int rr = w; rr < 24; rr += 16) {
        int row = (rr < 8)  ? (j0 + rr)
                : (rr < 16) ? (H_ + j0 + (rr - 8))
                            : (2 * H_ + j0 + (rr - 16));
        const float2* src = (const float2*)(Wh + (size_t)row * H_);
        for (int i = lane; i < 512; i += 32) {
            float2 v = __ldg(src + i);
            ws[rr * 512 + i] = pk2(v.x, v.y);
        }
    }

    // ---- init hidden state ----
    {
        int i = cta * 512 + tid;
        if (i < B_ * H_) {
            int b = i >> 10, j = i & 1023;
            g_h[i] = h0[(b * L_ + layer) * H_ + j];
        }
        if (w < 8) s_h[lane * 8 + w] = h0[(lane * L_ + layer) * H_ + j0 + w];
    }
    grid_barrier();

    ull v2[32];                        // operand regs, reused between phases

    for (int s = 0; s < S_; s++) {
        // ---- prefetch xp for this thread's epilogue column ----
        float xpA, xpB = 0.f;
        {
            const size_t base = (size_t)(s * B_ + lane) * G3H;
            int col = (w < 8) ? (j0 + w) : (H_ + j0 + (w - 8));
            xpA = __ldg(&xp[base + col]);
            if (w < 8) xpB = __ldg(&xp[base + 2 * H_ + j0 + w]);
        }

        // ---- load h k-slice into registers (L2-coherent, 16 LDG in flight) ----
        {
            const float4* hp = (const float4*)(g_h + lane * H_ + k0);
#pragma unroll
            for (int i = 0; i < 16; i++) {
                float4 v = __ldcg(hp + i);
                v2[2*i]   = pk2(v.x, v.y);
                v2[2*i+1] = pk2(v.z, v.w);
            }
        }

        // ---- phase A: 16 cols (8 z + 8 r), this warp's 64 k ----
#pragma unroll 2
        for (int c = 0; c < 16; c++) {
            const ulonglong2* wp = (const ulonglong2*)(ws + c * 512 + (k0 >> 1));
            ull a0 = 0, a1 = 0;
#pragma unroll 4
            for (int i = 0; i < 16; i++) {
                ulonglong2 u = wp[i];
                a0 = ffma2(v2[2*i],   u.x, a0);
                a1 = ffma2(v2[2*i+1], u.y, a1);
            }
            a0 = fadd2(a0, a1);
            float x, y; upk2(a0, x, y);
            red[(c * 32 + lane) * 17 + w] = x + y;
        }
        __syncthreads();

        // ---- reduce + gate epilogue: thread (c=w, b=lane) ----
        {
            const float* rp = red + (w * 32 + lane) * 17;
            float sum = xpA;
#pragma unroll
            for (int t = 0; t < 16; t++) sum += rp[t];
            float sg = 1.f / (1.f + expf(-sum));
            if (w < 8) {
                s_z[lane * 8 + w] = sg;
            } else {
                int c = w - 8;
                g_rh[lane * H_ + j0 + c] = sg * s_h[lane * 8 + c];
            }
        }
        grid_barrier();

        // ---- load rh k-slice (reuses v2) ----
        {
            const float4* rp4 = (const float4*)(g_rh + lane * H_ + k0);
#pragma unroll
            for (int i = 0; i < 16; i++) {
                float4 v = __ldcg(rp4 + i);
                v2[2*i]   = pk2(v.x, v.y);
                v2[2*i+1] = pk2(v.z, v.w);
            }
        }

        // ---- phase B: 8 g cols ----
#pragma unroll 2
        for (int c = 0; c < 8; c++) {
            const ulonglong2* wp = (const ulonglong2*)(ws + (16 + c) * 512 + (k0 >> 1));
            ull a0 = 0, a1 = 0;
#pragma unroll 4
            for (int i = 0; i < 16; i++) {
                ulonglong2 u = wp[i];
                a0 = ffma2(v2[2*i],   u.x, a0);
                a1 = ffma2(v2[2*i+1], u.y, a1);
            }
            a0 = fadd2(a0, a1);
            float x, y; upk2(a0, x, y);
            red[(c * 32 + lane) * 17 + w] = x + y;
        }
        __syncthreads();

        // ---- reduce + h update: thread (c=w<8, b=lane) ----
        if (w < 8) {
            const float* rp = red + (w * 32 + lane) * 17;
            float sum = xpB;
#pragma unroll
            for (int t = 0; t < 16; t++) sum += rp[t];
            float gg = tanhf(sum);
            float zz = s_z[lane * 8 + w];
            float ho = s_h[lane * 8 + w];
            float hn = zz * ho + (1.f - zz) * gg;
            int j = j0 + w;
            s_h[lane * 8 + w] = hn;
            g_h[lane * H_ + j] = hn;
            hs[(size_t)(s * B_ + lane) * H_ + j] = hn;
            if (s == S_ - 1) hlast[(size_t)(lane * L_ + layer) * H_ + j] = hn;
        }
        grid_barrier();
    }
}

// ---------------- host launch ----------------
extern "C" void kernel_launch(void* const* d_in, const int* in_sizes, int n_in,
                              void* d_out, int out_size)
{
    const float* x    = (const float*)d_in[0];
    const float* h0   = (const float*)d_in[1];
    const float* Wx0  = (const float*)d_in[2];
    const float* Wh0  = (const float*)d_in[3];
    const float* bh0  = (const float*)d_in[4];
    const float* Wx   = (const float*)d_in[5];
    const float* Wh   = (const float*)d_in[6];
    const float* bh   = (const float*)d_in[7];
    const float* Wout = (const float*)d_in[8];
    const float* bout = (const float*)d_in[9];

    float* out = (float*)d_out;
    float* hid = out + (size_t)B_ * S_ * O_;

    float *p_xT, *p_xp, *p_hs;
    cudaGetSymbolAddress((void**)&p_xT, g_xT);
    cudaGetSymbolAddress((void**)&p_xp, g_xp);
    cudaGetSymbolAddress((void**)&p_hs, g_hs);

    const int rec_smem = 24576 * 4 + 16 * 32 * 17 * 4;   // 98304 + 34816 = 133120
    cudaFuncSetAttribute(gru_rec_kernel,
                         cudaFuncAttributeMaxDynamicSharedMemorySize, rec_smem);

    // 1) transpose x -> [s*B+b][i]
    transpose_kernel<<<4096, 256>>>((const float4*)x, (float4*)p_xT);

    // 2) layer 0
    gemm_kernel<<<dim3(G3H / 128, (S_ * B_) / 128), 256>>>(p_xT, Wx0, bh0, p_xp, I_, G3H, 0);
    gru_rec_kernel<<<NCTA_REC, 512, rec_smem>>>(Wh0, p_xp, p_hs, h0, 0, hid);

    // 3) layer 1
    gemm_kernel<<<dim3(G3H / 128, (S_ * B_) / 128), 256>>>(p_hs, Wx, bh, p_xp, H_, G3H, 0);
    gru_rec_kernel<<<NCTA_REC, 512, rec_smem>>>(Wh, p_xp, p_hs, h0, 1, hid);

    // 4) layer 2
    gemm_kernel<<<dim3(G3H / 128, (S_ * B_) / 128), 256>>>(
        p_hs, Wx + (size_t)3 * H_ * H_, bh + 3 * H_, p_xp, H_, G3H, 0);
    gru_rec_kernel<<<NCTA_REC, 512, rec_smem>>>(
        Wh + (size_t)3 * H_ * H_, p_xp, p_hs, h0, 2, hid);

    // 5) output head -> d_out [B,S,O]
    gemm_kernel<<<dim3(O_ / 128, (S_ * B_) / 128), 256>>>(p_hs, Wout, bout, out, H_, O_, 1);
}

// round 8
// speedup vs baseline: 2.6658x; 2.4991x over previous
#include <cuda_runtime.h>
#include <math.h>

#define B_  32
#define S_  512
#define I_  256
#define H_  1024
#define O_  256
#define L_  3
#define G3H (3*H_)
#define NCTA_REC 128

typedef unsigned long long ull;

// ---------------- f32x2 packed math (sm_103a FFMA2 path) ----------------
__device__ __forceinline__ ull pk2(float x, float y) {
    ull r;
    asm("mov.b64 %0, {%1, %2};" : "=l"(r)
        : "r"(__float_as_uint(x)), "r"(__float_as_uint(y)));
    return r;
}
__device__ __forceinline__ void upk2(ull p, float& x, float& y) {
    unsigned int a, b;
    asm("mov.b64 {%0, %1}, %2;" : "=r"(a), "=r"(b) : "l"(p));
    x = __uint_as_float(a); y = __uint_as_float(b);
}
__device__ __forceinline__ ull ffma2(ull a, ull b, ull c) {
    ull d;
    asm("fma.rn.f32x2 %0, %1, %2, %3;" : "=l"(d) : "l"(a), "l"(b), "l"(c));
    return d;
}
__device__ __forceinline__ ull fadd2(ull a, ull b) {
    ull d;
    asm("add.rn.f32x2 %0, %1, %2;" : "=l"(d) : "l"(a), "l"(b));
    return d;
}

// ---------------- device scratch (allocation-free) ----------------
__device__ float g_xT[(size_t)S_*B_*I_];        // 16 MB  transposed x -> [s*B+b][i]
__device__ float g_xp[(size_t)S_*B_*G3H];       // 201 MB input projections [s*B+b][3H]
__device__ float g_hs[(size_t)S_*B_*H_];        // 64 MB  layer output sequence [s*B+b][h]
__device__ ull   g_hP [(H_/2)*B_];              // hidden, [kpair][b] packed f32x2
__device__ ull   g_rhP[(H_/2)*B_];              // r*h,    [kpair][b] packed f32x2
__device__ unsigned int g_barcount;
__device__ unsigned int g_bargen;

// ---------------- grid-wide barrier (proven R2 version) ----------------
__device__ __forceinline__ void grid_barrier()
{
    __syncthreads();
    if (threadIdx.x == 0) {
        unsigned int gen = *(volatile unsigned int*)&g_bargen;
        __threadfence();
        if (atomicAdd(&g_barcount, 1u) == gridDim.x - 1u) {
            g_barcount = 0u;
            __threadfence();
            atomicAdd(&g_bargen, 1u);
        } else {
            while (*(volatile unsigned int*)&g_bargen == gen) { __nanosleep(32); }
        }
        __threadfence();
    }
    __syncthreads();
}

// ---------------- transpose x[b][s][i] -> xT[(s*B+b)][i] ----------------
__global__ void transpose_kernel(const float4* __restrict__ x, float4* __restrict__ xT)
{
    int idx = blockIdx.x * blockDim.x + threadIdx.x;   // over S*B*I/4
    int i4 = idx & 63;          // I/4 = 64
    int m  = idx >> 6;          // m = s*B + b
    int b  = m & 31;
    int s  = m >> 5;
    xT[idx] = x[(size_t)(b * S_ + s) * 64 + i4];
}

// ---------------- SGEMM: C[m][n] = sum_k A[m][k]*W[n][k] + bias[n] ----------------
__global__ void __launch_bounds__(256) gemm_kernel(
    const float* __restrict__ A, const float* __restrict__ W,
    const float* __restrict__ bias, float* __restrict__ C,
    int K, int N, int mode)
{
    __shared__ float As[16][128];
    __shared__ float Bs[16][128];

    const int tid  = threadIdx.x;
    const int bx   = blockIdx.x;   // N tile
    const int by   = blockIdx.y;   // M tile
    const int lrow = tid >> 1;
    const int lc4  = (tid & 1) << 2;

    const float* Arow = A + (size_t)(by * 128 + lrow) * K + lc4;
    const float* Wrow = W + (size_t)(bx * 128 + lrow) * K + lc4;

    const int tx = tid & 15;
    const int ty = tid >> 4;

    ull acc2[8][4];
#pragma unroll
    for (int i = 0; i < 8; i++)
#pragma unroll
        for (int j = 0; j < 4; j++) acc2[i][j] = 0ull;

    for (int kt = 0; kt < K; kt += 16) {
        float4 a0 = *(const float4*)(Arow + kt);
        float4 a1 = *(const float4*)(Arow + kt + 8);
        float4 w0 = *(const float4*)(Wrow + kt);
        float4 w1 = *(const float4*)(Wrow + kt + 8);
        __syncthreads();
        As[lc4 + 0][lrow] = a0.x; As[lc4 + 1][lrow] = a0.y;
        As[lc4 + 2][lrow] = a0.z; As[lc4 + 3][lrow] = a0.w;
        As[lc4 + 8][lrow] = a1.x; As[lc4 + 9][lrow] = a1.y;
        As[lc4 +10][lrow] = a1.z; As[lc4 +11][lrow] = a1.w;
        Bs[lc4 + 0][lrow] = w0.x; Bs[lc4 + 1][lrow] = w0.y;
        Bs[lc4 + 2][lrow] = w0.z; Bs[lc4 + 3][lrow] = w0.w;
        Bs[lc4 + 8][lrow] = w1.x; Bs[lc4 + 9][lrow] = w1.y;
        Bs[lc4 +10][lrow] = w1.z; Bs[lc4 +11][lrow] = w1.w;
        __syncthreads();
#pragma unroll
        for (int k = 0; k < 16; k++) {
            float4 av0 = *(const float4*)&As[k][ty * 8];
            float4 av1 = *(const float4*)&As[k][ty * 8 + 4];
            float4 bv0 = *(const float4*)&Bs[k][tx * 8];
            float4 bv1 = *(const float4*)&Bs[k][tx * 8 + 4];
            ull pb0 = pk2(bv0.x, bv0.y);
            ull pb1 = pk2(bv0.z, bv0.w);
            ull pb2 = pk2(bv1.x, bv1.y);
            ull pb3 = pk2(bv1.z, bv1.w);
            float a_[8] = {av0.x, av0.y, av0.z, av0.w, av1.x, av1.y, av1.z, av1.w};
#pragma unroll
            for (int i = 0; i < 8; i++) {
                ull pa = pk2(a_[i], a_[i]);
                acc2[i][0] = ffma2(pa, pb0, acc2[i][0]);
                acc2[i][1] = ffma2(pa, pb1, acc2[i][1]);
                acc2[i][2] = ffma2(pa, pb2, acc2[i][2]);
                acc2[i][3] = ffma2(pa, pb3, acc2[i][3]);
            }
        }
    }

    const int mbase = by * 128 + ty * 8;
    const int nbase = bx * 128 + tx * 8;
    float bb[8];
#pragma unroll
    for (int j = 0; j < 8; j++) bb[j] = bias[nbase + j];

#pragma unroll
    for (int i = 0; i < 8; i++) {
        int m = mbase + i;
        float cv[8];
#pragma unroll
        for (int j = 0; j < 4; j++) upk2(acc2[i][j], cv[2*j], cv[2*j+1]);
#pragma unroll
        for (int j = 0; j < 8; j++) {
            float v = cv[j] + bb[j];
            if (mode == 0) {
                C[(size_t)m * N + (nbase + j)] = v;
            } else {
                int b = m & 31, s = m >> 5;
                C[(size_t)((b << 9) + s) * O_ + (nbase + j)] = v;
            }
        }
    }
}

// ---------------- persistent GRU recurrence (one layer) ----------------
// 128 CTAs (1/SM, co-resident), 512 threads = 16 warps.
// CTA owns gate columns [cta*8, cta*8+8) of z, r, g.
// Warp w = k-slice [w*64, w*64+64). lane = batch b.
// h and r*h live in [kpair][b] packed-f32x2 layout -> operand loads are
// LDG.64, fully coalesced (2 lines/warp), and arrive pre-packed for FFMA2.
// ALL register-array indices are compile-time constants (full unrolls).
__global__ void __launch_bounds__(512, 1) gru_rec_kernel(
    const float* __restrict__ Wh,      // [3H][H]
    const float* __restrict__ xp,      // [S*B][3H] (bias folded in)
    float*       __restrict__ hs,      // [S*B][H]
    const float* __restrict__ h0,      // [B][L][H]
    int layer,
    float*       __restrict__ hlast)   // d_out + B*S*O : [B][L][H]
{
    extern __shared__ float sh[];
    ull*   ws  = (ull*)sh;             // [24 cols][512 k-pairs]   96 KB
    float* red = sh + 24576;           // [16][32][17] partials    34 KB
    __shared__ float s_z[B_ * 8];      // z values   [b][c]
    __shared__ float s_h[B_ * 8];      // h (own 8 cols) [b][c]

    const int tid  = threadIdx.x;
    const int cta  = blockIdx.x;
    const int w    = tid >> 5;         // 0..15 : k-slice AND epilogue column
    const int lane = tid & 31;         // batch b
    const int j0   = cta * 8;
    const int kp0  = w * 32;           // base k-pair of this warp's slice

    float* hPf  = (float*)g_hP;
    float* rhPf = (float*)g_rhP;

    // ---- preload this CTA's 24 weight rows, packed k-pairs ----
    for (int rr = w; rr < 24; rr += 16) {
        int row = (rr < 8)  ? (j0 + rr)
                : (rr < 16) ? (H_ + j0 + (rr - 8))
                            : (2 * H_ + j0 + (rr - 16));
        const float2* src = (const float2*)(Wh + (size_t)row * H_);
        for (int i = lane; i < 512; i += 32) {
            float2 v = __ldg(src + i);
            ws[rr * 512 + i] = pk2(v.x, v.y);
        }
    }

    // ---- init hidden state: g_hP[(j>>1)*64 + b*2 + (j&1)] (as floats) ----
    {
        int i = cta * 512 + tid;
        if (i < B_ * H_) {
            int b = i >> 10, j = i & 1023;
            hPf[(j >> 1) * 64 + b * 2 + (j & 1)] = h0[(b * L_ + layer) * H_ + j];
        }
        if (w < 8) s_h[lane * 8 + w] = h0[(lane * L_ + layer) * H_ + j0 + w];
    }
    grid_barrier();

    ull v2[32];                        // operand regs, reused between phases

    for (int s = 0; s < S_; s++) {
        // ---- prefetch xp for this thread's epilogue column ----
        float xpA, xpB = 0.f;
        {
            const size_t base = (size_t)(s * B_ + lane) * G3H;
            int col = (w < 8) ? (j0 + w) : (H_ + j0 + (w - 8));
            xpA = __ldg(&xp[base + col]);
            if (w < 8) xpB = __ldg(&xp[base + 2 * H_ + j0 + w]);
        }

        // ---- load h k-slice: 32 coalesced LDG.64, already packed ----
        {
            const ull* hp = g_hP + (size_t)kp0 * 32 + lane;
#pragma unroll
            for (int i = 0; i < 32; i++)
                v2[i] = __ldcg(hp + i * 32);
        }

        // ---- phase A: 16 cols (8 z + 8 r), this warp's 64 k ----
#pragma unroll 2
        for (int c = 0; c < 16; c++) {
            const ulonglong2* wp = (const ulonglong2*)(ws + c * 512 + kp0);
            ull a0 = 0, a1 = 0;
#pragma unroll
            for (int i = 0; i < 16; i++) {
                ulonglong2 u = wp[i];
                a0 = ffma2(v2[2*i],   u.x, a0);
                a1 = ffma2(v2[2*i+1], u.y, a1);
            }
            a0 = fadd2(a0, a1);
            float x, y; upk2(a0, x, y);
            red[(c * 32 + lane) * 17 + w] = x + y;
        }
        __syncthreads();

        // ---- reduce + gate epilogue: thread (c=w, b=lane) ----
        {
            const float* rp = red + (w * 32 + lane) * 17;
            float sum = xpA;
#pragma unroll
            for (int t = 0; t < 16; t++) sum += rp[t];
            float sg = 1.f / (1.f + expf(-sum));
            if (w < 8) {
                s_z[lane * 8 + w] = sg;
            } else {
                int c = w - 8;
                int j = j0 + c;
                rhPf[(j >> 1) * 64 + lane * 2 + (j & 1)] = sg * s_h[lane * 8 + c];
            }
        }
        grid_barrier();

        // ---- load rh k-slice (reuses v2) ----
        {
            const ull* rp8 = g_rhP + (size_t)kp0 * 32 + lane;
#pragma unroll
            for (int i = 0; i < 32; i++)
                v2[i] = __ldcg(rp8 + i * 32);
        }

        // ---- phase B: 8 g cols ----
#pragma unroll 2
        for (int c = 0; c < 8; c++) {
            const ulonglong2* wp = (const ulonglong2*)(ws + (16 + c) * 512 + kp0);
            ull a0 = 0, a1 = 0;
#pragma unroll
            for (int i = 0; i < 16; i++) {
                ulonglong2 u = wp[i];
                a0 = ffma2(v2[2*i],   u.x, a0);
                a1 = ffma2(v2[2*i+1], u.y, a1);
            }
            a0 = fadd2(a0, a1);
            float x, y; upk2(a0, x, y);
            red[(c * 32 + lane) * 17 + w] = x + y;
        }
        __syncthreads();

        // ---- reduce + h update: thread (c=w<8, b=lane) ----
        if (w < 8) {
            const float* rp = red + (w * 32 + lane) * 17;
            float sum = xpB;
#pragma unroll
            for (int t = 0; t < 16; t++) sum += rp[t];
            float gg = tanhf(sum);
            float zz = s_z[lane * 8 + w];
            float ho = s_h[lane * 8 + w];
            float hn = zz * ho + (1.f - zz) * gg;
            int j = j0 + w;
            s_h[lane * 8 + w] = hn;
            hPf[(j >> 1) * 64 + lane * 2 + (j & 1)] = hn;
            hs[(size_t)(s * B_ + lane) * H_ + j] = hn;
            if (s == S_ - 1) hlast[(size_t)(lane * L_ + layer) * H_ + j] = hn;
        }
        grid_barrier();
    }
}

// ---------------- host launch ----------------
extern "C" void kernel_launch(void* const* d_in, const int* in_sizes, int n_in,
                              void* d_out, int out_size)
{
    const float* x    = (const float*)d_in[0];
    const float* h0   = (const float*)d_in[1];
    const float* Wx0  = (const float*)d_in[2];
    const float* Wh0  = (const float*)d_in[3];
    const float* bh0  = (const float*)d_in[4];
    const float* Wx   = (const float*)d_in[5];
    const float* Wh   = (const float*)d_in[6];
    const float* bh   = (const float*)d_in[7];
    const float* Wout = (const float*)d_in[8];
    const float* bout = (const float*)d_in[9];

    float* out = (float*)d_out;
    float* hid = out + (size_t)B_ * S_ * O_;

    float *p_xT, *p_xp, *p_hs;
    cudaGetSymbolAddress((void**)&p_xT, g_xT);
    cudaGetSymbolAddress((void**)&p_xp, g_xp);
    cudaGetSymbolAddress((void**)&p_hs, g_hs);

    const int rec_smem = 24576 * 4 + 16 * 32 * 17 * 4;   // 98304 + 34816 = 133120
    cudaFuncSetAttribute(gru_rec_kernel,
                         cudaFuncAttributeMaxDynamicSharedMemorySize, rec_smem);

    // 1) transpose x -> [s*B+b][i]
    transpose_kernel<<<4096, 256>>>((const float4*)x, (float4*)p_xT);

    // 2) layer 0
    gemm_kernel<<<dim3(G3H / 128, (S_ * B_) / 128), 256>>>(p_xT, Wx0, bh0, p_xp, I_, G3H, 0);
    gru_rec_kernel<<<NCTA_REC, 512, rec_smem>>>(Wh0, p_xp, p_hs, h0, 0, hid);

    // 3) layer 1
    gemm_kernel<<<dim3(G3H / 128, (S_ * B_) / 128), 256>>>(p_hs, Wx, bh, p_xp, H_, G3H, 0);
    gru_rec_kernel<<<NCTA_REC, 512, rec_smem>>>(Wh, p_xp, p_hs, h0, 1, hid);

    // 4) layer 2
    gemm_kernel<<<dim3(G3H / 128, (S_ * B_) / 128), 256>>>(
        p_hs, Wx + (size_t)3 * H_ * H_, bh + 3 * H_, p_xp, H_, G3H, 0);
    gru_rec_kernel<<<NCTA_REC, 512, rec_smem>>>(
        Wh + (size_t)3 * H_ * H_, p_xp, p_hs, h0, 2, hid);

    // 5) output head -> d_out [B,S,O]
    gemm_kernel<<<dim3(O_ / 128, (S_ * B_) / 128), 256>>>(p_hs, Wout, bout, out, H_, O_, 1);
}

// round 9
// speedup vs baseline: 2.7633x; 1.0366x over previous
#include <cuda_runtime.h>
#include <math.h>

#define B_  32
#define S_  512
#define I_  256
#define H_  1024
#define O_  256
#define L_  3
#define G3H (3*H_)
#define M_TOT (S_*B_)
#define NCTA_REC 128

typedef unsigned long long ull;

// ---------------- f32x2 packed math (sm_103a FFMA2 path) ----------------
__device__ __forceinline__ ull pk2(float x, float y) {
    ull r;
    asm("mov.b64 %0, {%1, %2};" : "=l"(r)
        : "r"(__float_as_uint(x)), "r"(__float_as_uint(y)));
    return r;
}
__device__ __forceinline__ void upk2(ull p, float& x, float& y) {
    unsigned int a, b;
    asm("mov.b64 {%0, %1}, %2;" : "=r"(a), "=r"(b) : "l"(p));
    x = __uint_as_float(a); y = __uint_as_float(b);
}
__device__ __forceinline__ ull ffma2(ull a, ull b, ull c) {
    ull d;
    asm("fma.rn.f32x2 %0, %1, %2, %3;" : "=l"(d) : "l"(a), "l"(b), "l"(c));
    return d;
}
__device__ __forceinline__ ull fadd2(ull a, ull b) {
    ull d;
    asm("add.rn.f32x2 %0, %1, %2;" : "=l"(d) : "l"(a), "l"(b));
    return d;
}

// ---------------- device scratch (allocation-free) ----------------
__device__ float g_xT[(size_t)M_TOT*I_];        // 16 MB  transposed x -> [s*B+b][i]
__device__ float g_xpT[(size_t)G3H*M_TOT];      // 201 MB xproj TRANSPOSED [col][s*B+b]
__device__ float g_hs[(size_t)M_TOT*H_];        // 64 MB  layer output sequence [s*B+b][h]
__device__ ull   g_hP [(H_/2)*B_];              // hidden, [kpair][b] packed f32x2
__device__ ull   g_rhP[(H_/2)*B_];              // r*h,    [kpair][b] packed f32x2
__device__ unsigned int g_barcount;
__device__ unsigned int g_bargen;

// ---------------- grid-wide barrier (proven version — do not touch) ----------------
__device__ __forceinline__ void grid_barrier()
{
    __syncthreads();
    if (threadIdx.x == 0) {
        unsigned int gen = *(volatile unsigned int*)&g_bargen;
        __threadfence();
        if (atomicAdd(&g_barcount, 1u) == gridDim.x - 1u) {
            g_barcount = 0u;
            __threadfence();
            atomicAdd(&g_bargen, 1u);
        } else {
            while (*(volatile unsigned int*)&g_bargen == gen) { __nanosleep(32); }
        }
        __threadfence();
    }
    __syncthreads();
}

// ---------------- transpose x[b][s][i] -> xT[(s*B+b)][i] ----------------
__global__ void transpose_kernel(const float4* __restrict__ x, float4* __restrict__ xT)
{
    int idx = blockIdx.x * blockDim.x + threadIdx.x;   // over S*B*I/4
    int i4 = idx & 63;          // I/4 = 64
    int m  = idx >> 6;          // m = s*B + b
    int b  = m & 31;
    int s  = m >> 5;
    xT[idx] = x[(size_t)(b * S_ + s) * 64 + i4];
}

// ---------------- SGEMM: C = A*W^T + bias, double-buffered smem ----------------
// mode 0: write TRANSPOSED  C_T[n][m]   (xproj -> g_xpT)
// mode 1: m=(s*B+b) -> C[(b*S+s)*O + n] (final output head)
__global__ void __launch_bounds__(256) gemm_kernel(
    const float* __restrict__ A, const float* __restrict__ W,
    const float* __restrict__ bias, float* __restrict__ C,
    int K, int N, int mode)
{
    __shared__ float As[2][16][128];
    __shared__ float Bs[2][16][128];

    const int tid  = threadIdx.x;
    const int bx   = blockIdx.x;   // N tile
    const int by   = blockIdx.y;   // M tile
    const int lrow = tid >> 1;
    const int lc4  = (tid & 1) << 2;

    const float* Arow = A + (size_t)(by * 128 + lrow) * K + lc4;
    const float* Wrow = W + (size_t)(bx * 128 + lrow) * K + lc4;

    const int tx = tid & 15;
    const int ty = tid >> 4;

    ull acc2[8][4];
#pragma unroll
    for (int i = 0; i < 8; i++)
#pragma unroll
        for (int j = 0; j < 4; j++) acc2[i][j] = 0ull;

    // prologue: tile 0 -> buf 0
    {
        float4 a0 = *(const float4*)(Arow);
        float4 a1 = *(const float4*)(Arow + 8);
        float4 w0 = *(const float4*)(Wrow);
        float4 w1 = *(const float4*)(Wrow + 8);
        As[0][lc4 + 0][lrow] = a0.x; As[0][lc4 + 1][lrow] = a0.y;
        As[0][lc4 + 2][lrow] = a0.z; As[0][lc4 + 3][lrow] = a0.w;
        As[0][lc4 + 8][lrow] = a1.x; As[0][lc4 + 9][lrow] = a1.y;
        As[0][lc4 +10][lrow] = a1.z; As[0][lc4 +11][lrow] = a1.w;
        Bs[0][lc4 + 0][lrow] = w0.x; Bs[0][lc4 + 1][lrow] = w0.y;
        Bs[0][lc4 + 2][lrow] = w0.z; Bs[0][lc4 + 3][lrow] = w0.w;
        Bs[0][lc4 + 8][lrow] = w1.x; Bs[0][lc4 + 9][lrow] = w1.y;
        Bs[0][lc4 +10][lrow] = w1.z; Bs[0][lc4 +11][lrow] = w1.w;
    }
    __syncthreads();

    int p = 0;
    for (int kt = 0; kt < K; kt += 16) {
        const bool nxt = (kt + 16) < K;
        float4 a0, a1, w0, w1;
        if (nxt) {                               // issue next-tile loads early
            a0 = *(const float4*)(Arow + kt + 16);
            a1 = *(const float4*)(Arow + kt + 24);
            w0 = *(const float4*)(Wrow + kt + 16);
            w1 = *(const float4*)(Wrow + kt + 24);
        }
#pragma unroll
        for (int k = 0; k < 16; k++) {
            float4 av0 = *(const float4*)&As[p][k][ty * 8];
            float4 av1 = *(const float4*)&As[p][k][ty * 8 + 4];
            float4 bv0 = *(const float4*)&Bs[p][k][tx * 8];
            float4 bv1 = *(const float4*)&Bs[p][k][tx * 8 + 4];
            ull pb0 = pk2(bv0.x, bv0.y);
            ull pb1 = pk2(bv0.z, bv0.w);
            ull pb2 = pk2(bv1.x, bv1.y);
            ull pb3 = pk2(bv1.z, bv1.w);
            float a_[8] = {av0.x, av0.y, av0.z, av0.w, av1.x, av1.y, av1.z, av1.w};
#pragma unroll
            for (int i = 0; i < 8; i++) {
                ull pa = pk2(a_[i], a_[i]);
                acc2[i][0] = ffma2(pa, pb0, acc2[i][0]);
                acc2[i][1] = ffma2(pa, pb1, acc2[i][1]);
                acc2[i][2] = ffma2(pa, pb2, acc2[i][2]);
                acc2[i][3] = ffma2(pa, pb3, acc2[i][3]);
            }
        }
        if (nxt) {
            const int q = p ^ 1;
            As[q][lc4 + 0][lrow] = a0.x; As[q][lc4 + 1][lrow] = a0.y;
            As[q][lc4 + 2][lrow] = a0.z; As[q][lc4 + 3][lrow] = a0.w;
            As[q][lc4 + 8][lrow] = a1.x; As[q][lc4 + 9][lrow] = a1.y;
            As[q][lc4 +10][lrow] = a1.z; As[q][lc4 +11][lrow] = a1.w;
            Bs[q][lc4 + 0][lrow] = w0.x; Bs[q][lc4 + 1][lrow] = w0.y;
            Bs[q][lc4 + 2][lrow] = w0.z; Bs[q][lc4 + 3][lrow] = w0.w;
            Bs[q][lc4 + 8][lrow] = w1.x; Bs[q][lc4 + 9][lrow] = w1.y;
            Bs[q][lc4 +10][lrow] = w1.z; Bs[q][lc4 +11][lrow] = w1.w;
            __syncthreads();
            p = q;
        }
    }

    const int mbase = by * 128 + ty * 8;
    const int nbase = bx * 128 + tx * 8;
    float bb[8];
#pragma unroll
    for (int j = 0; j < 8; j++) bb[j] = bias[nbase + j];

#pragma unroll
    for (int i = 0; i < 8; i++) {
        int m = mbase + i;
        float cv[8];
#pragma unroll
        for (int j = 0; j < 4; j++) upk2(acc2[i][j], cv[2*j], cv[2*j+1]);
#pragma unroll
        for (int j = 0; j < 8; j++) {
            float v = cv[j] + bb[j];
            if (mode == 0) {
                C[(size_t)(nbase + j) * M_TOT + m] = v;      // transposed
            } else {
                int b = m & 31, s = m >> 5;
                C[(size_t)((b << 9) + s) * O_ + (nbase + j)] = v;
            }
        }
    }
}

// ---------------- persistent GRU recurrence (one layer) ----------------
// 128 CTAs (1/SM, co-resident), 512 threads = 16 warps.
// CTA owns gate columns [cta*8, cta*8+8) of z, r, g.
// Warp w = k-slice [w*64, w*64+64). lane = batch b.
// h/r*h in [kpair][b] packed layout (coalesced LDG.64, pre-packed for FFMA2).
// xp in TRANSPOSED [col][m] layout -> epilogue fetches are coalesced too.
__global__ void __launch_bounds__(512, 1) gru_rec_kernel(
    const float* __restrict__ Wh,      // [3H][H]
    const float* __restrict__ xpT,     // [3H][S*B] (bias folded in)
    float*       __restrict__ hs,      // [S*B][H]
    const float* __restrict__ h0,      // [B][L][H]
    int layer,
    float*       __restrict__ hlast)   // d_out + B*S*O : [B][L][H]
{
    extern __shared__ float sh[];
    ull*   ws  = (ull*)sh;             // [24 cols][512 k-pairs]   96 KB
    float* red = sh + 24576;           // [16][32][17] partials    34 KB
    __shared__ float s_z[B_ * 8];      // z values   [b][c]
    __shared__ float s_h[B_ * 8];      // h (own 8 cols) [b][c]

    const int tid  = threadIdx.x;
    const int cta  = blockIdx.x;
    const int w    = tid >> 5;         // 0..15 : k-slice AND epilogue column
    const int lane = tid & 31;         // batch b
    const int j0   = cta * 8;
    const int kp0  = w * 32;           // base k-pair of this warp's slice

    float* hPf  = (float*)g_hP;
    float* rhPf = (float*)g_rhP;

    // ---- preload this CTA's 24 weight rows, packed k-pairs ----
    for (int rr = w; rr < 24; rr += 16) {
        int row = (rr < 8)  ? (j0 + rr)
                : (rr < 16) ? (H_ + j0 + (rr - 8))
                            : (2 * H_ + j0 + (rr - 16));
        const float2* src = (const float2*)(Wh + (size_t)row * H_);
        for (int i = lane; i < 512; i += 32) {
            float2 v = __ldg(src + i);
            ws[rr * 512 + i] = pk2(v.x, v.y);
        }
    }

    // ---- init hidden state: g_hP[(j>>1)*64 + b*2 + (j&1)] (as floats) ----
    {
        int i = cta * 512 + tid;
        if (i < B_ * H_) {
            int b = i >> 10, j = i & 1023;
            hPf[(j >> 1) * 64 + b * 2 + (j & 1)] = h0[(b * L_ + layer) * H_ + j];
        }
        if (w < 8) s_h[lane * 8 + w] = h0[(lane * L_ + layer) * H_ + j0 + w];
    }
    grid_barrier();

    // per-thread xp column bases (coalesced: lane-consecutive m)
    const float* xpColA = xpT + (size_t)((w < 8) ? (j0 + w) : (H_ + j0 + (w - 8))) * M_TOT;
    const float* xpColB = (w < 8) ? (xpT + (size_t)(2 * H_ + j0 + w) * M_TOT) : xpT;

    ull v2[32];                        // operand regs, reused between phases

    for (int s = 0; s < S_; s++) {
        // ---- prefetch xp for this thread's epilogue column (coalesced) ----
        const int m = s * B_ + lane;
        float xpA = __ldg(xpColA + m);
        float xpB = (w < 8) ? __ldg(xpColB + m) : 0.f;

        // ---- load h k-slice: 32 coalesced LDG.64, already packed ----
        {
            const ull* hp = g_hP + (size_t)kp0 * 32 + lane;
#pragma unroll
            for (int i = 0; i < 32; i++)
                v2[i] = __ldcg(hp + i * 32);
        }

        // ---- phase A: 16 cols (8 z + 8 r), this warp's 64 k ----
#pragma unroll 2
        for (int c = 0; c < 16; c++) {
            const ulonglong2* wp = (const ulonglong2*)(ws + c * 512 + kp0);
            ull a0 = 0, a1 = 0;
#pragma unroll
            for (int i = 0; i < 16; i++) {
                ulonglong2 u = wp[i];
                a0 = ffma2(v2[2*i],   u.x, a0);
                a1 = ffma2(v2[2*i+1], u.y, a1);
            }
            a0 = fadd2(a0, a1);
            float x, y; upk2(a0, x, y);
            red[(c * 32 + lane) * 17 + w] = x + y;
        }
        __syncthreads();

        // ---- reduce + gate epilogue: thread (c=w, b=lane) ----
        {
            const float* rp = red + (w * 32 + lane) * 17;
            float sum = xpA;
#pragma unroll
            for (int t = 0; t < 16; t++) sum += rp[t];
            float sg = 1.f / (1.f + expf(-sum));
            if (w < 8) {
                s_z[lane * 8 + w] = sg;
            } else {
                int c = w - 8;
                int j = j0 + c;
                rhPf[(j >> 1) * 64 + lane * 2 + (j & 1)] = sg * s_h[lane * 8 + c];
            }
        }
        grid_barrier();

        // ---- load rh k-slice (reuses v2) ----
        {
            const ull* rp8 = g_rhP + (size_t)kp0 * 32 + lane;
#pragma unroll
            for (int i = 0; i < 32; i++)
                v2[i] = __ldcg(rp8 + i * 32);
        }

        // ---- phase B: 8 g cols ----
#pragma unroll 2
        for (int c = 0; c < 8; c++) {
            const ulonglong2* wp = (const ulonglong2*)(ws + (16 + c) * 512 + kp0);
            ull a0 = 0, a1 = 0;
#pragma unroll
            for (int i = 0; i < 16; i++) {
                ulonglong2 u = wp[i];
                a0 = ffma2(v2[2*i],   u.x, a0);
                a1 = ffma2(v2[2*i+1], u.y, a1);
            }
            a0 = fadd2(a0, a1);
            float x, y; upk2(a0, x, y);
            red[(c * 32 + lane) * 17 + w] = x + y;
        }
        __syncthreads();

        // ---- reduce + h update: thread (c=w<8, b=lane) ----
        if (w < 8) {
            const float* rp = red + (w * 32 + lane) * 17;
            float sum = xpB;
#pragma unroll
            for (int t = 0; t < 16; t++) sum += rp[t];
            float gg = tanhf(sum);
            float zz = s_z[lane * 8 + w];
            float ho = s_h[lane * 8 + w];
            float hn = zz * ho + (1.f - zz) * gg;
            int j = j0 + w;
            s_h[lane * 8 + w] = hn;
            hPf[(j >> 1) * 64 + lane * 2 + (j & 1)] = hn;
            hs[(size_t)(s * B_ + lane) * H_ + j] = hn;
            if (s == S_ - 1) hlast[(size_t)(lane * L_ + layer) * H_ + j] = hn;
        }
        grid_barrier();
    }
}

// ---------------- host launch ----------------
extern "C" void kernel_launch(void* const* d_in, const int* in_sizes, int n_in,
                              void* d_out, int out_size)
{
    const float* x    = (const float*)d_in[0];
    const float* h0   = (const float*)d_in[1];
    const float* Wx0  = (const float*)d_in[2];
    const float* Wh0  = (const float*)d_in[3];
    const float* bh0  = (const float*)d_in[4];
    const float* Wx   = (const float*)d_in[5];
    const float* Wh   = (const float*)d_in[6];
    const float* bh   = (const float*)d_in[7];
    const float* Wout = (const float*)d_in[8];
    const float* bout = (const float*)d_in[9];

    float* out = (float*)d_out;
    float* hid = out + (size_t)B_ * S_ * O_;

    float *p_xT, *p_xpT, *p_hs;
    cudaGetSymbolAddress((void**)&p_xT, g_xT);
    cudaGetSymbolAddress((void**)&p_xpT, g_xpT);
    cudaGetSymbolAddress((void**)&p_hs, g_hs);

    const int rec_smem = 24576 * 4 + 16 * 32 * 17 * 4;   // 98304 + 34816 = 133120
    cudaFuncSetAttribute(gru_rec_kernel,
                         cudaFuncAttributeMaxDynamicSharedMemorySize, rec_smem);

    // 1) transpose x -> [s*B+b][i]
    transpose_kernel<<<4096, 256>>>((const float4*)x, (float4*)p_xT);

    // 2) layer 0
    gemm_kernel<<<dim3(G3H / 128, M_TOT / 128), 256>>>(p_xT, Wx0, bh0, p_xpT, I_, G3H, 0);
    gru_rec_kernel<<<NCTA_REC, 512, rec_smem>>>(Wh0, p_xpT, p_hs, h0, 0, hid);

    // 3) layer 1
    gemm_kernel<<<dim3(G3H / 128, M_TOT / 128), 256>>>(p_hs, Wx, bh, p_xpT, H_, G3H, 0);
    gru_rec_kernel<<<NCTA_REC, 512, rec_smem>>>(Wh, p_xpT, p_hs, h0, 1, hid);

    // 4) layer 2
    gemm_kernel<<<dim3(G3H / 128, M_TOT / 128), 256>>>(
        p_hs, Wx + (size_t)3 * H_ * H_, bh + 3 * H_, p_xpT, H_, G3H, 0);
    gru_rec_kernel<<<NCTA_REC, 512, rec_smem>>>(
        Wh + (size_t)3 * H_ * H_, p_xpT, p_hs, h0, 2, hid);

    // 5) output head -> d_out [B,S,O]
    gemm_kernel<<<dim3(O_ / 128, M_TOT / 128), 256>>>(p_hs, Wout, bout, out, H_, O_, 1);
}